// round 13
// baseline (speedup 1.0000x reference)
#include <cuda_runtime.h>
#include <cuda_fp16.h>
#include <cstdint>
#include <math.h>

#define H_DIM 128
#define R_DIM 6
#define D_DIM 256
#define MAX_NODES 50000

// Scratch
__device__ __align__(128) float g_agg[(size_t)MAX_NODES * H_DIM];   // 25.6 MB
__device__ __align__(128) float g_y0 [(size_t)MAX_NODES * D_DIM];   // 51.2 MB
__device__ __align__(128) float g_y1 [(size_t)MAX_NODES * D_DIM];   // 51.2 MB
// Pre-split weights (fp16 hi/lo): [0,32768) = W_up (256x128), then 3x Ws (256x256)
#define W_TOTAL (256*128 + 3*256*256)
__device__ __align__(128) __half g_whi[W_TOTAL];
__device__ __align__(128) __half g_wlo[W_TOTAL];

__device__ __forceinline__ uint32_t pack_h2(float a, float b) {
    __half2 v = __halves2half2(__float2half_rn(a), __float2half_rn(b));
    return *reinterpret_cast<uint32_t*>(&v);
}

// ---------------------------------------------------------------------------
// Prep kernels
// ---------------------------------------------------------------------------
__global__ void prep_w(const float* __restrict__ W_up, const float* __restrict__ Ws,
                       __half* __restrict__ whi, __half* __restrict__ wlo) {
    int i = blockIdx.x * blockDim.x + threadIdx.x;
    int stride = gridDim.x * blockDim.x;
    for (; i < W_TOTAL; i += stride) {
        float v = (i < 256 * 128) ? W_up[i] : Ws[i - 256 * 128];
        __half h = __float2half_rn(v);
        whi[i] = h;
        wlo[i] = __float2half_rn(v - __half2float(h));
    }
}

__global__ void zero_kernel(float4* __restrict__ p, int n4) {
    int i = blockIdx.x * blockDim.x + threadIdx.x;
    int stride = gridDim.x * blockDim.x;
    float4 z = make_float4(0.f, 0.f, 0.f, 0.f);
    for (; i < n4; i += stride) p[i] = z;
}

// ---------------------------------------------------------------------------
// Edge stage (round-5 proven best: 2 edges/warp-iter, 4ch/lane, red.v4)
// ---------------------------------------------------------------------------
__global__ void edge_kernel(const float* __restrict__ x,
                            const float* __restrict__ rbf,
                            const int*   __restrict__ idx,
                            const float* __restrict__ Wrbf,
                            float*       __restrict__ agg,
                            int E) {
    const int lane = threadIdx.x & 31;
    const int warp = (blockIdx.x * blockDim.x + threadIdx.x) >> 5;
    const int nwarps = (gridDim.x * blockDim.x) >> 5;

    float w[4][6];
    #pragma unroll
    for (int j = 0; j < 4; ++j)
        #pragma unroll
        for (int r = 0; r < R_DIM; ++r)
            w[j][r] = __ldg(Wrbf + (lane * 4 + j) * R_DIM + r);

    for (int e0 = warp * 2; e0 < E; e0 += nwarps * 2) {
        const int e1 = e0 + 1;
        const bool has1 = e1 < E;

        const float2* rp0 = reinterpret_cast<const float2*>(rbf + (size_t)e0 * R_DIM);
        float2 a01 = __ldg(rp0 + 0), a23 = __ldg(rp0 + 1), a45 = __ldg(rp0 + 2);
        int n0 = __ldg(idx + e0);
        float4 xv0 = __ldg(reinterpret_cast<const float4*>(x + (size_t)e0 * H_DIM) + lane);

        float2 b01 = a01, b23 = a23, b45 = a45;
        int n1 = n0;
        float4 xv1 = make_float4(0.f, 0.f, 0.f, 0.f);
        if (has1) {
            const float2* rp1 = reinterpret_cast<const float2*>(rbf + (size_t)e1 * R_DIM);
            b01 = __ldg(rp1 + 0); b23 = __ldg(rp1 + 1); b45 = __ldg(rp1 + 2);
            n1 = __ldg(idx + e1);
            xv1 = __ldg(reinterpret_cast<const float4*>(x + (size_t)e1 * H_DIM) + lane);
        }

        #pragma unroll
        for (int pass = 0; pass < 2; ++pass) {
            float2 r01 = pass ? b01 : a01;
            float2 r23 = pass ? b23 : a23;
            float2 r45 = pass ? b45 : a45;
            float4 xv  = pass ? xv1 : xv0;
            int node   = pass ? n1 : n0;
            if (pass && !has1) break;

            float g0 = w[0][0]*r01.x + w[0][1]*r01.y + w[0][2]*r23.x + w[0][3]*r23.y + w[0][4]*r45.x + w[0][5]*r45.y;
            float g1 = w[1][0]*r01.x + w[1][1]*r01.y + w[1][2]*r23.x + w[1][3]*r23.y + w[1][4]*r45.x + w[1][5]*r45.y;
            float g2 = w[2][0]*r01.x + w[2][1]*r01.y + w[2][2]*r23.x + w[2][3]*r23.y + w[2][4]*r45.x + w[2][5]*r45.y;
            float g3 = w[3][0]*r01.x + w[3][1]*r01.y + w[3][2]*r23.x + w[3][3]*r23.y + w[3][4]*r45.x + w[3][5]*r45.y;

            float vx = g0 * xv.x, vy = g1 * xv.y, vz = g2 * xv.z, vw = g3 * xv.w;
            float* dst = agg + (size_t)node * H_DIM + lane * 4;
            asm volatile("red.global.add.v4.f32 [%0], {%1, %2, %3, %4};"
                         :: "l"(dst), "f"(vx), "f"(vy), "f"(vz), "f"(vw) : "memory");
        }
    }
}

// ---------------------------------------------------------------------------
// Pipelined fp16-split GEMM (3 products, f32 acc).
// 512 threads, warp tile 32x32, CTA tile 128x128, K chunks of 64.
// Double-buffered SMEM (2 stages x 72KB), LDG->regs->STS pipeline, ldmatrix.
// ---------------------------------------------------------------------------
#define STRIDE_H 72                        // halfwords per SMEM row (64 data + 8 pad)
#define ARR_HW   (128 * STRIDE_H)          // 9216 halfwords per array
#define STAGE_HW (4 * ARR_HW)              // per-stage halfwords
#define SMEM_BYTES (2 * STAGE_HW * 2)      // 147456 bytes

__device__ __forceinline__ void mma_f16(float* d, const uint32_t* a, uint32_t b0, uint32_t b1) {
    asm("mma.sync.aligned.m16n8k16.row.col.f32.f16.f16.f32 "
        "{%0,%1,%2,%3}, {%4,%5,%6,%7}, {%8,%9}, {%0,%1,%2,%3};"
        : "+f"(d[0]), "+f"(d[1]), "+f"(d[2]), "+f"(d[3])
        : "r"(a[0]), "r"(a[1]), "r"(a[2]), "r"(a[3]), "r"(b0), "r"(b1));
}
__device__ __forceinline__ void ldsm4(uint32_t* r, uint32_t saddr) {
    asm volatile("ldmatrix.sync.aligned.m8n8.x4.shared.b16 {%0,%1,%2,%3}, [%4];"
                 : "=r"(r[0]), "=r"(r[1]), "=r"(r[2]), "=r"(r[3]) : "r"(saddr));
}

template<int K_TOTAL, bool BIAS, bool SILU, bool PROJ>
__global__ void __launch_bounds__(512, 1)
gemm_mma(const float* __restrict__ A,
         const __half* __restrict__ Bhi,
         const __half* __restrict__ Blo,
         const float* __restrict__ bias,
         const float* __restrict__ wout,
         float* __restrict__ Y,
         int M) {
    extern __shared__ __align__(16) uint16_t sm[];
    constexpr int NC = K_TOTAL / 64;

    const int tid  = threadIdx.x;
    const int wid  = tid >> 5, lane = tid & 31;
    const int g    = lane >> 2, t = lane & 3;
    const int m0   = blockIdx.x * 128;
    const int n0   = blockIdx.y * 128;
    const int wm   = (wid & 3) * 32;
    const int wn   = (wid >> 2) * 32;

    const uint32_t smem_b = (uint32_t)__cvta_generic_to_shared(sm);
    // ldmatrix lane addressing (halfword units within an array)
    const int arow = wm + (lane & 15);
    const int brow = wn + (lane & 15);
    const int khw  = (lane & 16) ? 8 : 0;

    float acc[2][4][4];
    #pragma unroll
    for (int i = 0; i < 2; ++i)
        #pragma unroll
        for (int j = 0; j < 4; ++j)
            #pragma unroll
            for (int q = 0; q < 4; ++q) acc[i][j][q] = 0.f;

    // prefetch registers
    float4 pfA[4];
    uint4  pfBh[2], pfBl[2];
    const int a_seg = tid & 15, a_rip = tid >> 4;   // 16 thr/row, rows 0..31 per pass
    const int b_seg = tid & 7,  b_rip = tid >> 3;   // 8 thr/row, rows 0..63 per pass

    auto ldg = [&](int c) {
        #pragma unroll
        for (int p = 0; p < 4; ++p) {
            const int grow = m0 + p * 32 + a_rip;
            pfA[p] = make_float4(0.f, 0.f, 0.f, 0.f);
            if (grow < M)
                pfA[p] = *reinterpret_cast<const float4*>(A + (size_t)grow * K_TOTAL + c * 64 + a_seg * 4);
        }
        #pragma unroll
        for (int p = 0; p < 2; ++p) {
            const size_t off = (size_t)(n0 + p * 64 + b_rip) * K_TOTAL + c * 64 + b_seg * 8;
            pfBh[p] = *reinterpret_cast<const uint4*>(Bhi + off);
            pfBl[p] = *reinterpret_cast<const uint4*>(Blo + off);
        }
    };
    auto sts = [&](int s) {
        uint16_t* sAhi = sm + s * STAGE_HW;
        uint16_t* sAlo = sAhi + ARR_HW;
        uint16_t* sBhi = sAhi + 2 * ARR_HW;
        uint16_t* sBlo = sAhi + 3 * ARR_HW;
        #pragma unroll
        for (int p = 0; p < 4; ++p) {
            float4 f = pfA[p];
            uint2 Hv, Lv;
            Hv.x = pack_h2(f.x, f.y);
            Hv.y = pack_h2(f.z, f.w);
            Lv.x = pack_h2(f.x - __half2float(__float2half_rn(f.x)),
                           f.y - __half2float(__float2half_rn(f.y)));
            Lv.y = pack_h2(f.z - __half2float(__float2half_rn(f.z)),
                           f.w - __half2float(__float2half_rn(f.w)));
            const int hw = (p * 32 + a_rip) * STRIDE_H + a_seg * 4;
            *reinterpret_cast<uint2*>(sAhi + hw) = Hv;
            *reinterpret_cast<uint2*>(sAlo + hw) = Lv;
        }
        #pragma unroll
        for (int p = 0; p < 2; ++p) {
            const int hw = (p * 64 + b_rip) * STRIDE_H + b_seg * 8;
            *reinterpret_cast<uint4*>(sBhi + hw) = pfBh[p];
            *reinterpret_cast<uint4*>(sBlo + hw) = pfBl[p];
        }
    };
    auto compute = [&](int s) {
        const uint32_t base  = smem_b + s * STAGE_HW * 2;
        const uint32_t aHiB  = base + (uint32_t)(arow * STRIDE_H + khw) * 2;
        const uint32_t aLoB  = aHiB + ARR_HW * 2;
        const uint32_t bHiB  = base + 2 * ARR_HW * 2 + (uint32_t)(brow * STRIDE_H + khw) * 2;
        const uint32_t bLoB  = bHiB + ARR_HW * 2;
        #pragma unroll
        for (int ks = 0; ks < 4; ++ks) {
            const uint32_t ko = (uint32_t)(ks * 16) * 2;
            uint32_t ahi[2][4], alo[2][4];
            #pragma unroll
            for (int i = 0; i < 2; ++i) {
                ldsm4(ahi[i], aHiB + ko + (uint32_t)(i * 16 * STRIDE_H) * 2);
                ldsm4(alo[i], aLoB + ko + (uint32_t)(i * 16 * STRIDE_H) * 2);
            }
            #pragma unroll
            for (int p = 0; p < 2; ++p) {
                uint32_t bh[4], bl[4];
                ldsm4(bh, bHiB + ko + (uint32_t)(p * 16 * STRIDE_H) * 2);
                ldsm4(bl, bLoB + ko + (uint32_t)(p * 16 * STRIDE_H) * 2);
                #pragma unroll
                for (int i = 0; i < 2; ++i) {
                    // j = 2p   : b0 = r0, b1 = r2
                    mma_f16(acc[i][2 * p],     ahi[i], bh[0], bh[2]);
                    mma_f16(acc[i][2 * p],     ahi[i], bl[0], bl[2]);
                    mma_f16(acc[i][2 * p],     alo[i], bh[0], bh[2]);
                    // j = 2p+1 : b0 = r1, b1 = r3
                    mma_f16(acc[i][2 * p + 1], ahi[i], bh[1], bh[3]);
                    mma_f16(acc[i][2 * p + 1], ahi[i], bl[1], bl[3]);
                    mma_f16(acc[i][2 * p + 1], alo[i], bh[1], bh[3]);
                }
            }
        }
    };

    // ---- pipeline ----
    ldg(0);
    sts(0);
    if (NC > 1) ldg(1);
    __syncthreads();
    for (int c = 0; c < NC; ++c) {
        compute(c & 1);
        if (c + 1 < NC) {
            sts((c + 1) & 1);
            if (c + 2 < NC) ldg(c + 2);
            __syncthreads();
        }
    }

    // ---- epilogue ----
    if (PROJ) {
        float s4[4] = {0.f, 0.f, 0.f, 0.f};
        #pragma unroll
        for (int i = 0; i < 2; ++i)
            #pragma unroll
            for (int j = 0; j < 4; ++j) {
                int col = n0 + wn + j * 8 + t * 2;
                float w0 = __ldg(wout + col), w1 = __ldg(wout + col + 1);
                float b0 = BIAS ? __ldg(bias + col) : 0.f;
                float b1 = BIAS ? __ldg(bias + col + 1) : 0.f;
                float v0 = acc[i][j][0] + b0, v1 = acc[i][j][1] + b1;
                float v2 = acc[i][j][2] + b0, v3 = acc[i][j][3] + b1;
                if (SILU) {
                    v0 = v0 / (1.f + __expf(-v0)); v1 = v1 / (1.f + __expf(-v1));
                    v2 = v2 / (1.f + __expf(-v2)); v3 = v3 / (1.f + __expf(-v3));
                }
                s4[i * 2 + 0] += v0 * w0 + v1 * w1;
                s4[i * 2 + 1] += v2 * w0 + v3 * w1;
            }
        #pragma unroll
        for (int q = 0; q < 4; ++q) {
            s4[q] += __shfl_xor_sync(0xffffffffu, s4[q], 1);
            s4[q] += __shfl_xor_sync(0xffffffffu, s4[q], 2);
        }
        if (t == 0) {
            #pragma unroll
            for (int i = 0; i < 2; ++i) {
                int r0 = m0 + wm + i * 16 + g;
                if (r0 < M)
                    asm volatile("red.global.add.f32 [%0], %1;" :: "l"(Y + r0), "f"(s4[i*2]) : "memory");
                if (r0 + 8 < M)
                    asm volatile("red.global.add.f32 [%0], %1;" :: "l"(Y + r0 + 8), "f"(s4[i*2+1]) : "memory");
            }
        }
    } else {
        #pragma unroll
        for (int i = 0; i < 2; ++i) {
            int r0 = m0 + wm + i * 16 + g;
            #pragma unroll
            for (int j = 0; j < 4; ++j) {
                int col = n0 + wn + j * 8 + t * 2;
                float b0 = BIAS ? __ldg(bias + col) : 0.f;
                float b1 = BIAS ? __ldg(bias + col + 1) : 0.f;
                float v0 = acc[i][j][0] + b0, v1 = acc[i][j][1] + b1;
                float v2 = acc[i][j][2] + b0, v3 = acc[i][j][3] + b1;
                if (SILU) {
                    v0 = v0 / (1.f + __expf(-v0)); v1 = v1 / (1.f + __expf(-v1));
                    v2 = v2 / (1.f + __expf(-v2)); v3 = v3 / (1.f + __expf(-v3));
                }
                if (r0 < M)
                    *reinterpret_cast<float2*>(Y + (size_t)r0 * D_DIM + col) = make_float2(v0, v1);
                if (r0 + 8 < M)
                    *reinterpret_cast<float2*>(Y + (size_t)(r0 + 8) * D_DIM + col) = make_float2(v2, v3);
            }
        }
    }
}

// ---------------------------------------------------------------------------
// Launch
// Inputs: 0:x[E,128] 1:rbf[E,6] 2:i[E] 3:W_rbf[128,6] 4:W_up[256,128]
//         5:Ws[3,256,256] 6:bs[3,256] 7:W_out[1,256] (8:num_nodes)
// ---------------------------------------------------------------------------
extern "C" void kernel_launch(void* const* d_in, const int* in_sizes, int n_in,
                              void* d_out, int out_size) {
    const float* x     = (const float*)d_in[0];
    const float* rbf   = (const float*)d_in[1];
    const int*   idx   = (const int*)  d_in[2];
    const float* W_rbf = (const float*)d_in[3];
    const float* W_up  = (const float*)d_in[4];
    const float* Ws    = (const float*)d_in[5];
    const float* bs    = (const float*)d_in[6];
    const float* W_out = (const float*)d_in[7];
    float* out = (float*)d_out;

    const int E = in_sizes[2];
    const int M = out_size;

    float *agg, *y0, *y1;
    __half *whi, *wlo;
    cudaGetSymbolAddress((void**)&agg, g_agg);
    cudaGetSymbolAddress((void**)&y0,  g_y0);
    cudaGetSymbolAddress((void**)&y1,  g_y1);
    cudaGetSymbolAddress((void**)&whi, g_whi);
    cudaGetSymbolAddress((void**)&wlo, g_wlo);

    cudaFuncSetAttribute(gemm_mma<128, false, false, false>, cudaFuncAttributeMaxDynamicSharedMemorySize, SMEM_BYTES);
    cudaFuncSetAttribute(gemm_mma<256, true,  true,  false>, cudaFuncAttributeMaxDynamicSharedMemorySize, SMEM_BYTES);
    cudaFuncSetAttribute(gemm_mma<256, true,  true,  true >, cudaFuncAttributeMaxDynamicSharedMemorySize, SMEM_BYTES);

    prep_w<<<224, 256>>>(W_up, Ws, whi, wlo);
    zero_kernel<<<1024, 256>>>((float4*)agg, M * H_DIM / 4);
    zero_kernel<<<128, 256>>>((float4*)out, M / 4);

    edge_kernel<<<1184, 256>>>(x, rbf, idx, W_rbf, agg, E);

    const int tiles = (M + 127) / 128;
    dim3 grid(tiles, 2);
    const __half* whi_l = whi + 256 * 128;
    const __half* wlo_l = wlo + 256 * 128;

    // up-projection: y0 = agg @ W_up^T
    gemm_mma<128, false, false, false><<<grid, 512, SMEM_BYTES>>>(agg, whi, wlo, nullptr, nullptr, y0, M);
    // layer 0: y1 = silu(y0 @ W0^T + b0)
    gemm_mma<256, true, true, false><<<grid, 512, SMEM_BYTES>>>(y0, whi_l + 0*65536, wlo_l + 0*65536, bs + 0*D_DIM, nullptr, y1, M);
    // layer 1: y0 = silu(y1 @ W1^T + b1)
    gemm_mma<256, true, true, false><<<grid, 512, SMEM_BYTES>>>(y1, whi_l + 1*65536, wlo_l + 1*65536, bs + 1*D_DIM, nullptr, y0, M);
    // layer 2 + fused projection into out
    gemm_mma<256, true, true, true ><<<grid, 512, SMEM_BYTES>>>(y0, whi_l + 2*65536, wlo_l + 2*65536, bs + 2*D_DIM, W_out, out, M);
}

// round 14
// speedup vs baseline: 1.1591x; 1.1591x over previous
#include <cuda_runtime.h>
#include <cuda_fp16.h>
#include <cstdint>
#include <math.h>

#define H_DIM 128
#define R_DIM 6
#define D_DIM 256
#define MAX_NODES 50000

// Scratch
__device__ __align__(128) float g_agg[(size_t)MAX_NODES * H_DIM];   // 25.6 MB
__device__ __align__(128) float g_y0 [(size_t)MAX_NODES * D_DIM];   // 51.2 MB
__device__ __align__(128) float g_y1 [(size_t)MAX_NODES * D_DIM];   // 51.2 MB
// Pre-split weights (fp16 hi/lo): [0,32768) = W_up (256x128), then 3x Ws (256x256)
#define W_TOTAL (256*128 + 3*256*256)
__device__ __align__(128) __half g_whi[W_TOTAL];
__device__ __align__(128) __half g_wlo[W_TOTAL];

__device__ __forceinline__ uint32_t pack_h2(float a, float b) {
    __half2 v = __halves2half2(__float2half_rn(a), __float2half_rn(b));
    return *reinterpret_cast<uint32_t*>(&v);
}

// ---------------------------------------------------------------------------
// Prep kernels
// ---------------------------------------------------------------------------
__global__ void prep_w(const float* __restrict__ W_up, const float* __restrict__ Ws,
                       __half* __restrict__ whi, __half* __restrict__ wlo) {
    int i = blockIdx.x * blockDim.x + threadIdx.x;
    int stride = gridDim.x * blockDim.x;
    for (; i < W_TOTAL; i += stride) {
        float v = (i < 256 * 128) ? W_up[i] : Ws[i - 256 * 128];
        __half h = __float2half_rn(v);
        whi[i] = h;
        wlo[i] = __float2half_rn(v - __half2float(h));
    }
}

__global__ void zero_kernel(float4* __restrict__ p, int n4) {
    int i = blockIdx.x * blockDim.x + threadIdx.x;
    int stride = gridDim.x * blockDim.x;
    float4 z = make_float4(0.f, 0.f, 0.f, 0.f);
    for (; i < n4; i += stride) p[i] = z;
}

// ---------------------------------------------------------------------------
// Edge stage (round-5 proven best: 2 edges/warp-iter, 4ch/lane, red.v4)
// ---------------------------------------------------------------------------
__global__ void edge_kernel(const float* __restrict__ x,
                            const float* __restrict__ rbf,
                            const int*   __restrict__ idx,
                            const float* __restrict__ Wrbf,
                            float*       __restrict__ agg,
                            int E) {
    const int lane = threadIdx.x & 31;
    const int warp = (blockIdx.x * blockDim.x + threadIdx.x) >> 5;
    const int nwarps = (gridDim.x * blockDim.x) >> 5;

    float w[4][6];
    #pragma unroll
    for (int j = 0; j < 4; ++j)
        #pragma unroll
        for (int r = 0; r < R_DIM; ++r)
            w[j][r] = __ldg(Wrbf + (lane * 4 + j) * R_DIM + r);

    for (int e0 = warp * 2; e0 < E; e0 += nwarps * 2) {
        const int e1 = e0 + 1;
        const bool has1 = e1 < E;

        const float2* rp0 = reinterpret_cast<const float2*>(rbf + (size_t)e0 * R_DIM);
        float2 a01 = __ldg(rp0 + 0), a23 = __ldg(rp0 + 1), a45 = __ldg(rp0 + 2);
        int n0 = __ldg(idx + e0);
        float4 xv0 = __ldg(reinterpret_cast<const float4*>(x + (size_t)e0 * H_DIM) + lane);

        float2 b01 = a01, b23 = a23, b45 = a45;
        int n1 = n0;
        float4 xv1 = make_float4(0.f, 0.f, 0.f, 0.f);
        if (has1) {
            const float2* rp1 = reinterpret_cast<const float2*>(rbf + (size_t)e1 * R_DIM);
            b01 = __ldg(rp1 + 0); b23 = __ldg(rp1 + 1); b45 = __ldg(rp1 + 2);
            n1 = __ldg(idx + e1);
            xv1 = __ldg(reinterpret_cast<const float4*>(x + (size_t)e1 * H_DIM) + lane);
        }

        #pragma unroll
        for (int pass = 0; pass < 2; ++pass) {
            float2 r01 = pass ? b01 : a01;
            float2 r23 = pass ? b23 : a23;
            float2 r45 = pass ? b45 : a45;
            float4 xv  = pass ? xv1 : xv0;
            int node   = pass ? n1 : n0;
            if (pass && !has1) break;

            float g0 = w[0][0]*r01.x + w[0][1]*r01.y + w[0][2]*r23.x + w[0][3]*r23.y + w[0][4]*r45.x + w[0][5]*r45.y;
            float g1 = w[1][0]*r01.x + w[1][1]*r01.y + w[1][2]*r23.x + w[1][3]*r23.y + w[1][4]*r45.x + w[1][5]*r45.y;
            float g2 = w[2][0]*r01.x + w[2][1]*r01.y + w[2][2]*r23.x + w[2][3]*r23.y + w[2][4]*r45.x + w[2][5]*r45.y;
            float g3 = w[3][0]*r01.x + w[3][1]*r01.y + w[3][2]*r23.x + w[3][3]*r23.y + w[3][4]*r45.x + w[3][5]*r45.y;

            float vx = g0 * xv.x, vy = g1 * xv.y, vz = g2 * xv.z, vw = g3 * xv.w;
            float* dst = agg + (size_t)node * H_DIM + lane * 4;
            asm volatile("red.global.add.v4.f32 [%0], {%1, %2, %3, %4};"
                         :: "l"(dst), "f"(vx), "f"(vy), "f"(vz), "f"(vw) : "memory");
        }
    }
}

// ---------------------------------------------------------------------------
// fp16-split GEMM, 2 products (Ahi*Bhi + Ahi*Blo), f32 acc, K-chunk 64.
// A converted on the fly to fp16 hi only (error ~2^-12.6, within tolerance).
// CTA tile 128x128, 8 warps of 32x64, dynamic SMEM 54KB, 2 CTAs/SM.
// ---------------------------------------------------------------------------
#define STRIDE_H 72            // halfwords per SMEM row (64 data + 8 pad)
#define ARR_HW   (128 * STRIDE_H)          // 9216 halfwords per array
#define SMEM_BYTES (3 * ARR_HW * 2)        // 55296 bytes (Ahi, Bhi, Blo)

__device__ __forceinline__ void mma_f16(float* d, const uint32_t* a, uint32_t b0, uint32_t b1) {
    asm("mma.sync.aligned.m16n8k16.row.col.f32.f16.f16.f32 "
        "{%0,%1,%2,%3}, {%4,%5,%6,%7}, {%8,%9}, {%0,%1,%2,%3};"
        : "+f"(d[0]), "+f"(d[1]), "+f"(d[2]), "+f"(d[3])
        : "r"(a[0]), "r"(a[1]), "r"(a[2]), "r"(a[3]), "r"(b0), "r"(b1));
}

template<int K_TOTAL, bool BIAS, bool SILU, bool PROJ>
__global__ void __launch_bounds__(256, 2)
gemm_mma(const float* __restrict__ A,
         const __half* __restrict__ Bhi,
         const __half* __restrict__ Blo,
         const float* __restrict__ bias,
         const float* __restrict__ wout,
         float* __restrict__ Y,
         int M) {
    extern __shared__ __align__(16) uint16_t sm[];
    uint16_t* sAhi = sm;
    uint16_t* sBhi = sm + ARR_HW;
    uint16_t* sBlo = sm + 2 * ARR_HW;

    const int tid  = threadIdx.x;
    const int wid  = tid >> 5, lane = tid & 31;
    const int g    = lane >> 2, t = lane & 3;
    const int m0   = blockIdx.x * 128;
    const int n0   = blockIdx.y * 128;
    const int wm   = (wid & 3) * 32;
    const int wn   = (wid >> 2) * 64;

    float acc[2][8][4];
    #pragma unroll
    for (int i = 0; i < 2; ++i)
        #pragma unroll
        for (int j = 0; j < 8; ++j)
            #pragma unroll
            for (int q = 0; q < 4; ++q) acc[i][j][q] = 0.f;

    const uint32_t* A32hi = reinterpret_cast<const uint32_t*>(sAhi);
    const uint32_t* B32hi = reinterpret_cast<const uint32_t*>(sBhi);
    const uint32_t* B32lo = reinterpret_cast<const uint32_t*>(sBlo);

    // A fill: 16 threads/row (1 float4 each), 16 rows/pass, 8 passes
    const int a_seg = tid & 15;
    const int a_rip = tid >> 4;
    // B fill: 8 threads/row (1 uint4 = 8 halves each), 32 rows/pass, 4 passes
    const int b_seg = tid & 7;
    const int b_rip = tid >> 3;

    for (int c = 0; c < K_TOTAL / 64; ++c) {
        // ---- fill A (fp32 -> fp16 hi only), coalesced ----
        #pragma unroll
        for (int p = 0; p < 8; ++p) {
            const int row = p * 16 + a_rip;
            const int grow = m0 + row;
            float4 f = make_float4(0.f, 0.f, 0.f, 0.f);
            if (grow < M)
                f = *reinterpret_cast<const float4*>(A + (size_t)grow * K_TOTAL + c * 64 + a_seg * 4);
            uint2 Hv;
            Hv.x = pack_h2(f.x, f.y);
            Hv.y = pack_h2(f.z, f.w);
            *reinterpret_cast<uint2*>(sAhi + row * STRIDE_H + a_seg * 4) = Hv;
        }
        // ---- fill B (hi + lo), coalesced ----
        #pragma unroll
        for (int p = 0; p < 4; ++p) {
            const int row = p * 32 + b_rip;
            const size_t off = (size_t)(n0 + row) * K_TOTAL + c * 64 + b_seg * 8;
            uint4 bh = *reinterpret_cast<const uint4*>(Bhi + off);
            uint4 bl = *reinterpret_cast<const uint4*>(Blo + off);
            const int hw = row * STRIDE_H + b_seg * 8;
            *reinterpret_cast<uint4*>(sBhi + hw) = bh;
            *reinterpret_cast<uint4*>(sBlo + hw) = bl;
        }
        __syncthreads();

        // ---- compute: 4 k16-steps x 2 products ----
        #pragma unroll
        for (int ks = 0; ks < 4; ++ks) {
            const int kw = ks * 8;
            uint32_t ahi[2][4];
            #pragma unroll
            for (int i = 0; i < 2; ++i) {
                int r0 = (wm + i * 16 + g) * (STRIDE_H / 2) + kw + t;
                ahi[i][0] = A32hi[r0];        ahi[i][1] = A32hi[r0 + 8 * (STRIDE_H / 2)];
                ahi[i][2] = A32hi[r0 + 4];    ahi[i][3] = A32hi[r0 + 8 * (STRIDE_H / 2) + 4];
            }
            #pragma unroll
            for (int j = 0; j < 8; ++j) {
                int nb = (wn + j * 8 + g) * (STRIDE_H / 2) + kw + t;
                uint32_t bh0 = B32hi[nb], bh1 = B32hi[nb + 4];
                uint32_t bl0 = B32lo[nb], bl1 = B32lo[nb + 4];
                #pragma unroll
                for (int i = 0; i < 2; ++i) {
                    mma_f16(acc[i][j], ahi[i], bh0, bh1);
                    mma_f16(acc[i][j], ahi[i], bl0, bl1);
                }
            }
        }
        __syncthreads();
    }

    // ---- epilogue ----
    if (PROJ) {
        float s[4] = {0.f, 0.f, 0.f, 0.f};
        #pragma unroll
        for (int i = 0; i < 2; ++i)
            #pragma unroll
            for (int j = 0; j < 8; ++j) {
                int col = n0 + wn + j * 8 + t * 2;
                float w0 = __ldg(wout + col), w1 = __ldg(wout + col + 1);
                float b0 = BIAS ? __ldg(bias + col) : 0.f;
                float b1 = BIAS ? __ldg(bias + col + 1) : 0.f;
                float v0 = acc[i][j][0] + b0, v1 = acc[i][j][1] + b1;
                float v2 = acc[i][j][2] + b0, v3 = acc[i][j][3] + b1;
                if (SILU) {
                    v0 = v0 / (1.f + __expf(-v0)); v1 = v1 / (1.f + __expf(-v1));
                    v2 = v2 / (1.f + __expf(-v2)); v3 = v3 / (1.f + __expf(-v3));
                }
                s[i * 2 + 0] += v0 * w0 + v1 * w1;
                s[i * 2 + 1] += v2 * w0 + v3 * w1;
            }
        #pragma unroll
        for (int q = 0; q < 4; ++q) {
            s[q] += __shfl_xor_sync(0xffffffffu, s[q], 1);
            s[q] += __shfl_xor_sync(0xffffffffu, s[q], 2);
        }
        if (t == 0) {
            #pragma unroll
            for (int i = 0; i < 2; ++i) {
                int r0 = m0 + wm + i * 16 + g;
                if (r0 < M)
                    asm volatile("red.global.add.f32 [%0], %1;" :: "l"(Y + r0), "f"(s[i*2]) : "memory");
                if (r0 + 8 < M)
                    asm volatile("red.global.add.f32 [%0], %1;" :: "l"(Y + r0 + 8), "f"(s[i*2+1]) : "memory");
            }
        }
    } else {
        #pragma unroll
        for (int i = 0; i < 2; ++i) {
            int r0 = m0 + wm + i * 16 + g;
            #pragma unroll
            for (int j = 0; j < 8; ++j) {
                int col = n0 + wn + j * 8 + t * 2;
                float b0 = BIAS ? __ldg(bias + col) : 0.f;
                float b1 = BIAS ? __ldg(bias + col + 1) : 0.f;
                float v0 = acc[i][j][0] + b0, v1 = acc[i][j][1] + b1;
                float v2 = acc[i][j][2] + b0, v3 = acc[i][j][3] + b1;
                if (SILU) {
                    v0 = v0 / (1.f + __expf(-v0)); v1 = v1 / (1.f + __expf(-v1));
                    v2 = v2 / (1.f + __expf(-v2)); v3 = v3 / (1.f + __expf(-v3));
                }
                if (r0 < M)
                    *reinterpret_cast<float2*>(Y + (size_t)r0 * D_DIM + col) = make_float2(v0, v1);
                if (r0 + 8 < M)
                    *reinterpret_cast<float2*>(Y + (size_t)(r0 + 8) * D_DIM + col) = make_float2(v2, v3);
            }
        }
    }
}

// ---------------------------------------------------------------------------
// Launch
// Inputs: 0:x[E,128] 1:rbf[E,6] 2:i[E] 3:W_rbf[128,6] 4:W_up[256,128]
//         5:Ws[3,256,256] 6:bs[3,256] 7:W_out[1,256] (8:num_nodes)
// ---------------------------------------------------------------------------
extern "C" void kernel_launch(void* const* d_in, const int* in_sizes, int n_in,
                              void* d_out, int out_size) {
    const float* x     = (const float*)d_in[0];
    const float* rbf   = (const float*)d_in[1];
    const int*   idx   = (const int*)  d_in[2];
    const float* W_rbf = (const float*)d_in[3];
    const float* W_up  = (const float*)d_in[4];
    const float* Ws    = (const float*)d_in[5];
    const float* bs    = (const float*)d_in[6];
    const float* W_out = (const float*)d_in[7];
    float* out = (float*)d_out;

    const int E = in_sizes[2];
    const int M = out_size;

    float *agg, *y0, *y1;
    __half *whi, *wlo;
    cudaGetSymbolAddress((void**)&agg, g_agg);
    cudaGetSymbolAddress((void**)&y0,  g_y0);
    cudaGetSymbolAddress((void**)&y1,  g_y1);
    cudaGetSymbolAddress((void**)&whi, g_whi);
    cudaGetSymbolAddress((void**)&wlo, g_wlo);

    cudaFuncSetAttribute(gemm_mma<128, false, false, false>, cudaFuncAttributeMaxDynamicSharedMemorySize, SMEM_BYTES);
    cudaFuncSetAttribute(gemm_mma<256, true,  true,  false>, cudaFuncAttributeMaxDynamicSharedMemorySize, SMEM_BYTES);
    cudaFuncSetAttribute(gemm_mma<256, true,  true,  true >, cudaFuncAttributeMaxDynamicSharedMemorySize, SMEM_BYTES);

    prep_w<<<224, 256>>>(W_up, Ws, whi, wlo);
    zero_kernel<<<1024, 256>>>((float4*)agg, M * H_DIM / 4);
    zero_kernel<<<128, 256>>>((float4*)out, M / 4);

    edge_kernel<<<1184, 256>>>(x, rbf, idx, W_rbf, agg, E);

    const int tiles = (M + 127) / 128;
    dim3 grid(tiles, 2);
    const __half* whi_l = whi + 256 * 128;
    const __half* wlo_l = wlo + 256 * 128;

    // up-projection: y0 = agg @ W_up^T
    gemm_mma<128, false, false, false><<<grid, 256, SMEM_BYTES>>>(agg, whi, wlo, nullptr, nullptr, y0, M);
    // layer 0: y1 = silu(y0 @ W0^T + b0)
    gemm_mma<256, true, true, false><<<grid, 256, SMEM_BYTES>>>(y0, whi_l + 0*65536, wlo_l + 0*65536, bs + 0*D_DIM, nullptr, y1, M);
    // layer 1: y0 = silu(y1 @ W1^T + b1)
    gemm_mma<256, true, true, false><<<grid, 256, SMEM_BYTES>>>(y1, whi_l + 1*65536, wlo_l + 1*65536, bs + 1*D_DIM, nullptr, y0, M);
    // layer 2 + fused projection into out
    gemm_mma<256, true, true, true ><<<grid, 256, SMEM_BYTES>>>(y0, whi_l + 2*65536, wlo_l + 2*65536, bs + 2*D_DIM, W_out, out, M);
}